// round 5
// baseline (speedup 1.0000x reference)
#include <cuda_runtime.h>

// Problem constants (from reference: B=16, L=192, E=128, T=25)
#define BB   16
#define LL   192
#define EE   128
#define TT   25
#define NI   (LL - TT - 1)          // 166 block rows per batch
#define LOUT (TT + 1 + NI * LL)     // 31898 output rows per batch
#define E2   (EE / 2)               // 64 float2 per row
#define G    6                      // i-values per block (tail tile predicated)
#define NT   ((NI + G - 1) / G)     // 28 i-tiles
#define NZ   4                      // l-slices per (tile,b)
#define LCH  (LL / NZ)              // 48 l-values per slice

// Scratch: s0[b,l,e] = sigmoid(x*(W0-W1) + (b0-b1)). 1.5 MB (L2-resident).
__device__ float g_S[BB * LL * EE];

// Kernel 1: compute s0 table once; also copy the 26-row head x[:, :T+1, :] -> out.
__global__ void prep_kernel(const float* __restrict__ x,
                            const float* __restrict__ W,
                            const float* __restrict__ bvec,
                            float* __restrict__ out) {
    int idx = blockIdx.x * blockDim.x + threadIdx.x;
    float dw = W[0] - W[1];
    float db = bvec[0] - bvec[1];
    if (idx < BB * LL * EE) {
        float v = x[idx];
        float z = fmaf(v, dw, db);
        g_S[idx] = __frcp_rn(1.0f + __expf(-z));   // sigmoid
    }
    if (idx < BB * (TT + 1) * EE) {
        int e = idx % EE;
        int t = (idx / EE) % (TT + 1);
        int b = idx / (EE * (TT + 1));
        out[((size_t)b * LOUT + t) * EE + e] = x[((size_t)b * LL + t) * EE + e];
    }
}

// Kernel 2: blocks[b,i,l,:] = fma(xi - xp, s0[b,l,:], xp)
// Grid: (28 i-tiles, 16 batches, 4 l-slices) = 1792 CTAs, 256 threads.
// G=6 i-values held in registers per CTA -> each S-table value loaded once
// serves 6 output rows (read overhead 2/48 + 1/6 = 0.21 vs 0.58 before),
// cutting L2-ring read traffic ~3x. Streaming stores for the 261 MB output.
__global__ void __launch_bounds__(256, 6)
blocks_kernel(const float* __restrict__ x, float* __restrict__ out) {
    const int b    = blockIdx.y;
    const int tile = blockIdx.x;
    const int zl   = blockIdx.z;
    const int tid  = threadIdx.x;
    const int lsub = tid >> 6;       // 0..3
    const int e2   = tid & 63;       // 0..63

    const float2* __restrict__ x2 = reinterpret_cast<const float2*>(x);
    const float2* __restrict__ S2 = reinterpret_cast<const float2*>(g_S);
    float2* __restrict__ o2       = reinterpret_cast<float2*>(out);

    const int ibase = tile * G;

    float2 dd[G], pp[G];
#pragma unroll
    for (int g = 0; g < G; g++) {
        int i = ibase + g;
        int ic = (i < NI) ? i : (NI - 1);   // clamp loads for the tail tile
        float2 a = __ldg(&x2[((size_t)b * LL + (TT + 1 + ic)) * E2 + e2]);  // xi
        float2 p = __ldg(&x2[((size_t)b * LL + (ic + 1)) * E2 + e2]);       // xp
        pp[g] = p;
        dd[g].x = a.x - p.x;
        dd[g].y = a.y - p.y;
    }

    const float2* __restrict__ Sb = S2 + (size_t)b * LL * E2;
    const size_t outrow0 = (size_t)b * LOUT + (TT + 1);
    const int lbeg = zl * LCH;
    const int nvalid = NI - ibase;   // >= G for all but the last tile

#pragma unroll 4
    for (int l0 = 0; l0 < LCH; l0 += 4) {
        const int l = lbeg + l0 + lsub;
        float2 s = __ldg(&Sb[(size_t)l * E2 + e2]);
#pragma unroll
        for (int g = 0; g < G; g++) {
            if (g < nvalid) {
                float2 o;
                o.x = fmaf(dd[g].x, s.x, pp[g].x);
                o.y = fmaf(dd[g].y, s.y, pp[g].y);
                __stcs(&o2[(outrow0 + (size_t)(ibase + g) * LL + l) * E2 + e2], o);
            }
        }
    }
}

extern "C" void kernel_launch(void* const* d_in, const int* in_sizes, int n_in,
                              void* d_out, int out_size) {
    const float* x  = (const float*)d_in[0];
    const float* W  = (const float*)d_in[1];
    const float* bv = (const float*)d_in[2];
    float* out = (float*)d_out;

    int n1 = BB * LL * EE;
    prep_kernel<<<(n1 + 255) / 256, 256>>>(x, W, bv, out);

    dim3 grid(NT, BB, NZ);   // (28, 16, 4) = 1792 CTAs
    blocks_kernel<<<grid, 256>>>(x, out);
}

// round 6
// speedup vs baseline: 1.5350x; 1.5350x over previous
#include <cuda_runtime.h>
#include <cstdint>

// Problem constants (from reference: B=16, L=192, E=128, T=25)
#define BB   16
#define LL   192
#define EE   128
#define TT   25
#define NI   (LL - TT - 1)          // 166 block rows per batch
#define LOUT (TT + 1 + NI * LL)     // 31898 output rows per batch
#define E2   (EE / 2)               // 64 float2 per row
#define G    4                      // i-values per CTA (tail tile predicated)
#define NT   ((NI + G - 1) / G)     // 42 i-tiles
#define NZ   4                      // l-slices per (tile,b)
#define LCH  (LL / NZ)              // 48 l-values per slice
#define CL   8                      // l-rows per chunk
#define NCH  (LCH / CL)             // 6 chunks per CTA

// Scratch: s0[b,l,e] = sigmoid(x*(W0-W1) + (b0-b1)). 1.5 MB (L2-resident).
__device__ float g_S[BB * LL * EE];

__device__ __forceinline__ uint32_t smem_u32(const void* p) {
    uint32_t a;
    asm("{ .reg .u64 t; cvta.to.shared.u64 t, %1; cvt.u32.u64 %0, t; }"
        : "=r"(a) : "l"(p));
    return a;
}

// Kernel 1: compute s0 table once; also copy the 26-row head x[:, :T+1, :] -> out.
__global__ void prep_kernel(const float* __restrict__ x,
                            const float* __restrict__ W,
                            const float* __restrict__ bvec,
                            float* __restrict__ out) {
    int idx = blockIdx.x * blockDim.x + threadIdx.x;
    float dw = W[0] - W[1];
    float db = bvec[0] - bvec[1];
    if (idx < BB * LL * EE) {
        float v = x[idx];
        float z = fmaf(v, dw, db);
        g_S[idx] = __frcp_rn(1.0f + __expf(-z));   // sigmoid
    }
    if (idx < BB * (TT + 1) * EE) {
        int e = idx % EE;
        int t = (idx / EE) % (TT + 1);
        int b = idx / (EE * (TT + 1));
        out[((size_t)b * LOUT + t) * EE + e] = x[((size_t)b * LL + t) * EE + e];
    }
}

// Kernel 2: blocks[b,i,l,:] = fma(xi - xp, s0[b,l,:], xp)
// Grid (42,16,4) = 2688 CTAs, 256 threads. Output produced in SMEM and drained
// with TMA bulk stores (bypasses L1tex / SM store issue). Double-buffered
// 2 x 16 KB; each chunk = 4 contiguous 4 KB regions (one per i).
__global__ void __launch_bounds__(256, 6)
blocks_kernel(const float* __restrict__ x, float* __restrict__ out) {
    __shared__ __align__(16) float2 sbuf[2][G][CL][E2];   // 2 x 16 KB

    const int b    = blockIdx.y;
    const int tile = blockIdx.x;
    const int zl   = blockIdx.z;
    const int tid  = threadIdx.x;
    const int r    = tid >> 6;       // 0..3  (l-row within half-chunk)
    const int e2   = tid & 63;       // 0..63 (float2 lane)

    const float2* __restrict__ x2 = reinterpret_cast<const float2*>(x);
    const float2* __restrict__ S2 = reinterpret_cast<const float2*>(g_S);

    const int ibase = tile * G;

    // Per-thread xi/xp state for G i-values (depends only on g, e2).
    float2 dd[G], pp[G];
#pragma unroll
    for (int g = 0; g < G; g++) {
        int i = ibase + g;
        int ic = (i < NI) ? i : (NI - 1);   // clamp loads on tail tile
        float2 a = __ldg(&x2[((size_t)b * LL + (TT + 1 + ic)) * E2 + e2]);  // xi
        float2 p = __ldg(&x2[((size_t)b * LL + (ic + 1)) * E2 + e2]);       // xp
        pp[g] = p;
        dd[g].x = a.x - p.x;
        dd[g].y = a.y - p.y;
    }

    const float2* __restrict__ Sb = S2 + (size_t)b * LL * E2;
    const size_t outrow0 = (size_t)b * LOUT + (TT + 1);
    const int lbeg = zl * LCH;

    for (int c = 0; c < NCH; c++) {
        const int buf = c & 1;
        // Before overwriting this buffer, ensure its store group (issued 2
        // iterations ago) drained: allow at most 1 group in flight.
        if (tid == 0)
            asm volatile("cp.async.bulk.wait_group 1;" ::: "memory");
        __syncthreads();

        const int lb = lbeg + c * CL;
#pragma unroll
        for (int step = 0; step < CL / 4; step++) {
            const int ll = step * 4 + r;
            float2 s = __ldg(&Sb[(size_t)(lb + ll) * E2 + e2]);
#pragma unroll
            for (int g = 0; g < G; g++) {
                float2 o;
                o.x = fmaf(dd[g].x, s.x, pp[g].x);
                o.y = fmaf(dd[g].y, s.y, pp[g].y);
                sbuf[buf][g][ll][e2] = o;
            }
        }
        __syncthreads();

        if (tid == 0) {
            asm volatile("fence.proxy.async.shared::cta;" ::: "memory");
#pragma unroll
            for (int g = 0; g < G; g++) {
                if (ibase + g < NI) {
                    const float* dst =
                        out + (outrow0 + (size_t)(ibase + g) * LL + lb) * EE;
                    uint32_t src = smem_u32(&sbuf[buf][g][0][0]);
                    asm volatile(
                        "cp.async.bulk.global.shared::cta.bulk_group [%0], [%1], %2;"
                        :: "l"(dst), "r"(src), "r"(CL * EE * 4) : "memory");
                }
            }
            asm volatile("cp.async.bulk.commit_group;" ::: "memory");
        }
    }

    // Drain all pending bulk stores before exit.
    if (tid == 0)
        asm volatile("cp.async.bulk.wait_group 0;" ::: "memory");
}

extern "C" void kernel_launch(void* const* d_in, const int* in_sizes, int n_in,
                              void* d_out, int out_size) {
    const float* x  = (const float*)d_in[0];
    const float* W  = (const float*)d_in[1];
    const float* bv = (const float*)d_in[2];
    float* out = (float*)d_out;

    int n1 = BB * LL * EE;
    prep_kernel<<<(n1 + 255) / 256, 256>>>(x, W, bv, out);

    dim3 grid(NT, BB, NZ);   // (42, 16, 4) = 2688 CTAs
    blocks_kernel<<<grid, 256>>>(x, out);
}

// round 7
// speedup vs baseline: 1.6527x; 1.0767x over previous
#include <cuda_runtime.h>

// Problem constants (from reference: B=16, L=192, E=128, T=25)
#define BB   16
#define LL   192
#define EE   128
#define TT   25
#define NI   (LL - TT - 1)          // 166 block rows per batch
#define LOUT (TT + 1 + NI * LL)     // 31898 output rows per batch
#define E2   (EE / 2)               // 64 float2 per row
#define G    4                      // i-values per block (tail predicated)
#define NT   ((NI + G - 1) / G)     // 42 i-tiles
#define NZ   8                      // l-slices per (tile,b)
#define LCH  (LL / NZ)              // 24 l-values per slice

// Scratch: s0[b,l,e] = sigmoid(x*(W0-W1) + (b0-b1)). 1.5 MB (L2-resident).
__device__ float g_S[BB * LL * EE];

// Kernel 1: compute s0 table once; also copy the 26-row head x[:, :T+1, :] -> out.
__global__ void prep_kernel(const float* __restrict__ x,
                            const float* __restrict__ W,
                            const float* __restrict__ bvec,
                            float* __restrict__ out) {
    int idx = blockIdx.x * blockDim.x + threadIdx.x;
    float dw = W[0] - W[1];
    float db = bvec[0] - bvec[1];
    if (idx < BB * LL * EE) {
        float v = x[idx];
        float z = fmaf(v, dw, db);
        g_S[idx] = __frcp_rn(1.0f + __expf(-z));   // sigmoid
    }
    if (idx < BB * (TT + 1) * EE) {
        int e = idx % EE;
        int t = (idx / EE) % (TT + 1);
        int b = idx / (EE * (TT + 1));
        out[((size_t)b * LOUT + t) * EE + e] = x[((size_t)b * LL + t) * EE + e];
    }
}

// Kernel 2: blocks[b,i,l,:] = fma(xi - xp, s0[b,l,:], xp)
// Grid: (42 i-tiles, 16 batches, 8 l-slices) = 5376 CTAs, 256 threads.
// float2 lanes: e2 = tid%64 spans the row, lsub = tid/64 covers 4 l's per step.
// Plain write-back stores: lets ~126 MB of the output stream stay L2-resident
// across graph replays instead of force-draining 261 MB to DRAM every launch.
__global__ void __launch_bounds__(256, 8)
blocks_kernel(const float* __restrict__ x, float* __restrict__ out) {
    const int b    = blockIdx.y;
    const int tile = blockIdx.x;
    const int zl   = blockIdx.z;
    const int tid  = threadIdx.x;
    const int lsub = tid >> 6;       // 0..3
    const int e2   = tid & 63;       // 0..63

    const float2* __restrict__ x2 = reinterpret_cast<const float2*>(x);
    const float2* __restrict__ S2 = reinterpret_cast<const float2*>(g_S);
    float2* __restrict__ o2       = reinterpret_cast<float2*>(out);

    const int ibase = tile * G;

    float2 dd[G], pp[G];
#pragma unroll
    for (int g = 0; g < G; g++) {
        int i = ibase + g;
        int ic = (i < NI) ? i : (NI - 1);   // clamp loads on tail tile
        float2 a = __ldg(&x2[((size_t)b * LL + (TT + 1 + ic)) * E2 + e2]);  // xi
        float2 p = __ldg(&x2[((size_t)b * LL + (ic + 1)) * E2 + e2]);       // xp
        pp[g] = p;
        dd[g].x = a.x - p.x;
        dd[g].y = a.y - p.y;
    }

    const float2* __restrict__ Sb = S2 + (size_t)b * LL * E2;
    const size_t outrow0 = (size_t)b * LOUT + (TT + 1);
    const int lbeg = zl * LCH;
    const int nvalid = NI - ibase;   // >= G except on the last i-tile

#pragma unroll
    for (int l0 = 0; l0 < LCH; l0 += 4) {
        const int l = lbeg + l0 + lsub;
        float2 s = __ldg(&Sb[(size_t)l * E2 + e2]);
#pragma unroll
        for (int g = 0; g < G; g++) {
            if (g < nvalid) {
                float2 o;
                o.x = fmaf(dd[g].x, s.x, pp[g].x);
                o.y = fmaf(dd[g].y, s.y, pp[g].y);
                o2[(outrow0 + (size_t)(ibase + g) * LL + l) * E2 + e2] = o;
            }
        }
    }
}

extern "C" void kernel_launch(void* const* d_in, const int* in_sizes, int n_in,
                              void* d_out, int out_size) {
    const float* x  = (const float*)d_in[0];
    const float* W  = (const float*)d_in[1];
    const float* bv = (const float*)d_in[2];
    float* out = (float*)d_out;

    int n1 = BB * LL * EE;
    prep_kernel<<<(n1 + 255) / 256, 256>>>(x, W, bv, out);

    dim3 grid(NT, BB, NZ);   // (42, 16, 8) = 5376 CTAs
    blocks_kernel<<<grid, 256>>>(x, out);
}

// round 8
// speedup vs baseline: 1.7350x; 1.0498x over previous
#include <cuda_runtime.h>

// Problem constants (from reference: B=16, L=192, E=128, T=25)
#define BB   16
#define LL   192
#define EE   128
#define TT   25
#define NI   (LL - TT - 1)          // 166 block rows per batch (even)
#define LOUT (TT + 1 + NI * LL)     // 31898 output rows per batch
#define E2   (EE / 2)               // 64 float2 per row
#define G    2                      // i-values per block (166 % 2 == 0, no tail)
#define NZ   8                      // l-slices per (tile,b)
#define LCH  (LL / NZ)              // 24 l-values per slice

// Scratch: s0[b,l,e] = sigmoid(x*(W0-W1) + (b0-b1)). 1.5 MB (L2-resident).
__device__ float g_S[BB * LL * EE];

// Kernel 1: compute s0 table once; also copy the 26-row head x[:, :T+1, :] -> out.
__global__ void prep_kernel(const float* __restrict__ x,
                            const float* __restrict__ W,
                            const float* __restrict__ bvec,
                            float* __restrict__ out) {
    int idx = blockIdx.x * blockDim.x + threadIdx.x;
    float dw = W[0] - W[1];
    float db = bvec[0] - bvec[1];
    if (idx < BB * LL * EE) {
        float v = x[idx];
        float z = fmaf(v, dw, db);
        g_S[idx] = __frcp_rn(1.0f + __expf(-z));   // sigmoid
    }
    if (idx < BB * (TT + 1) * EE) {
        int e = idx % EE;
        int t = (idx / EE) % (TT + 1);
        int b = idx / (EE * (TT + 1));
        out[((size_t)b * LOUT + t) * EE + e] = x[((size_t)b * LL + t) * EE + e];
    }
}

// Kernel 2: blocks[b,i,l,:] = fma(xi - xp, s0[b,l,:], xp)
// Grid: (83 i-tiles, 16 batches, 8 l-slices) = 10624 CTAs, 256 threads.
// e2 = tid%64 is the float2 lane, lsub = tid/64 covers 4 l's per iteration.
// All addressing hoisted into pointer increments; inner body is
// 1 LDG.64 + 4 FMA + 2 STG.64 (streaming). __stcs keeps L2 clean for the
// hot S-table/x reads during warm graph replays (timed-best in R3/R4).
__global__ void __launch_bounds__(256, 8)
blocks_kernel(const float* __restrict__ x, float* __restrict__ out) {
    const int b    = blockIdx.y;
    const int tile = blockIdx.x;
    const int zl   = blockIdx.z;
    const int tid  = threadIdx.x;
    const int lsub = tid >> 6;       // 0..3
    const int e2   = tid & 63;       // 0..63

    const float2* __restrict__ x2 = reinterpret_cast<const float2*>(x);

    const int ibase = tile * G;
    const int i0 = ibase;
    const int i1 = ibase + 1;

    // Per-thread xi/xp state (depends only on g, e2).
    float2 a0 = __ldg(&x2[((size_t)b * LL + (TT + 1 + i0)) * E2 + e2]);
    float2 p0 = __ldg(&x2[((size_t)b * LL + (i0 + 1)) * E2 + e2]);
    float2 a1 = __ldg(&x2[((size_t)b * LL + (TT + 1 + i1)) * E2 + e2]);
    float2 p1 = __ldg(&x2[((size_t)b * LL + (i1 + 1)) * E2 + e2]);
    float2 d0 = make_float2(a0.x - p0.x, a0.y - p0.y);
    float2 d1 = make_float2(a1.x - p1.x, a1.y - p1.y);

    const int lbeg = zl * LCH;
    const size_t outrow0 = (size_t)b * LOUT + (TT + 1);

    // Hoisted pointers; all advance by 4 rows (4*E2 float2) per iteration.
    const float2* __restrict__ sp =
        reinterpret_cast<const float2*>(g_S) +
        ((size_t)b * LL + lbeg + lsub) * E2 + e2;
    float2* __restrict__ q0 =
        reinterpret_cast<float2*>(out) +
        (outrow0 + (size_t)i0 * LL + lbeg + lsub) * E2 + e2;
    float2* __restrict__ q1 =
        reinterpret_cast<float2*>(out) +
        (outrow0 + (size_t)i1 * LL + lbeg + lsub) * E2 + e2;

#pragma unroll
    for (int it = 0; it < LCH / 4; it++) {
        float2 s = __ldg(sp);
        float2 o0, o1;
        o0.x = fmaf(d0.x, s.x, p0.x);
        o0.y = fmaf(d0.y, s.y, p0.y);
        o1.x = fmaf(d1.x, s.x, p1.x);
        o1.y = fmaf(d1.y, s.y, p1.y);
        __stcs(q0, o0);
        __stcs(q1, o1);
        sp += 4 * E2;
        q0 += 4 * E2;
        q1 += 4 * E2;
    }
}

extern "C" void kernel_launch(void* const* d_in, const int* in_sizes, int n_in,
                              void* d_out, int out_size) {
    const float* x  = (const float*)d_in[0];
    const float* W  = (const float*)d_in[1];
    const float* bv = (const float*)d_in[2];
    float* out = (float*)d_out;

    int n1 = BB * LL * EE;
    prep_kernel<<<(n1 + 255) / 256, 256>>>(x, W, bv, out);

    dim3 grid(NI / G, BB, NZ);   // (83, 16, 8) = 10624 CTAs
    blocks_kernel<<<grid, 256>>>(x, out);
}